// round 4
// baseline (speedup 1.0000x reference)
#include <cuda_runtime.h>
#include <cuda_bf16.h>

// RITS recurrence v3: persistent CTAs, 512 threads (16 warps) per CTA.
//  - 128 CTAs x 512 thr, 2 samples/CTA, full T=512 on-chip.
//  - Phase C: thread = (k-half, output col); W_lstm/U_lstm halves in regs
//    (96 regs/thread), partials reduced in C2.
//  - Phase B: fused [W_feat_c ; W_beta] vs concat act [xc|gx|m], 8 slices.
//  - All GEMMs packed fma.rn.f32x2, k-pair-interleaved smem weights.

#define TT 512
#define NIMP (256L * 3 * 512 * 64)
typedef unsigned long long ull;

#define FMA2(acc, a, b) \
    asm("fma.rn.f32x2 %0, %1, %2, %0;" : "+l"(acc) : "l"(a), "l"(b))

__device__ __forceinline__ ull pk2(float x, float y) {
    ull r; asm("mov.b64 %0, {%1, %2};" : "=l"(r) : "f"(x), "f"(y)); return r;
}
__device__ __forceinline__ float2 upk(ull v) {
    float2 r; asm("mov.b64 {%0, %1}, %2;" : "=f"(r.x), "=f"(r.y) : "l"(v)); return r;
}

__global__ __launch_bounds__(512, 1) void rits_kernel(
    const float* __restrict__ inputs,
    const float* __restrict__ W_hist, const float* __restrict__ b_hist,
    const float* __restrict__ W_feat, const float* __restrict__ b_feat,
    const float* __restrict__ W_gx,   const float* __restrict__ b_gx,
    const float* __restrict__ W_gh,   const float* __restrict__ b_gh,
    const float* __restrict__ W_beta, const float* __restrict__ b_beta,
    const float* __restrict__ W_lstm, const float* __restrict__ U_lstm,
    const float* __restrict__ b_lstm,
    const float* __restrict__ W_out,  const float* __restrict__ b_out,
    float* __restrict__ out)
{
    extern __shared__ __align__(16) float sm[];
    float* sWh2  = sm;             // 4096  W_hist pairs {w[2q][j],w[2q+1][j]}
    float* sWgh2 = sWh2  + 4096;   // 4096  W_gh pairs
    float* sWzb  = sWgh2 + 4096;   // 12288 [W_feat_c(32 pairs) ; W_beta(64 pairs)]
    float* sWgx  = sWzb + 12288;   // 64    diag(W_gx)
    float* sbh   = sWgx + 64;
    float* sbf   = sbh  + 64;
    float* sbgx  = sbf  + 64;
    float* sbb   = sbgx + 64;
    float* sbgh  = sbb  + 64;
    float* sbl   = sbgh + 64;      // 256
    float* hS    = sbl  + 256;     // 128  h[s][j]
    float* cS    = hS   + 128;     // 128
    float* hdec  = cS   + 128;     // 128
    float* xhat  = hdec + 128;     // 128
    float* ccm   = xhat + 128;     // 256  [s][cc(64)|m(64)]
    float* actB  = ccm  + 256;     // 384  [s][xc(64)|gx(64)|m(64)]
    float* pA    = actB + 384;     // 1024 [(g*4+kq)][s][j]
    float* pz    = pA   + 1024;    // 384  3 slices x [s][j]
    float* pb    = pz   + 384;     // 768  6 slices x [s][j]
    float* pC    = pb   + 768;     // 1024 [(kh*2+s)][o]
    float* inb   = pC   + 1024;    // 2*384 double-buffered [c][s][64]

    const int tid = threadIdx.x;
    const int bid = blockIdx.x;

    // ---- pack smem weights ----
    for (int i = tid; i < 2048; i += 512) {
        int q = i >> 6, j = i & 63;
        *(float2*)&sWh2[i * 2]  = make_float2(W_hist[(2*q)*64 + j], W_hist[(2*q+1)*64 + j]);
        *(float2*)&sWgh2[i * 2] = make_float2(W_gh[(2*q)*64 + j],   W_gh[(2*q+1)*64 + j]);
    }
    for (int i = tid; i < 6144; i += 512) {
        int q = i >> 6, j = i & 63;
        float a, b;
        if (q < 32) {
            int k0 = 2 * q;
            a = (k0     == j) ? 0.f : W_feat[k0 * 64 + j];
            b = (k0 + 1 == j) ? 0.f : W_feat[(k0 + 1) * 64 + j];
        } else {
            int k0 = 2 * (q - 32);
            a = W_beta[k0 * 64 + j];
            b = W_beta[(k0 + 1) * 64 + j];
        }
        *(float2*)&sWzb[i * 2] = make_float2(a, b);
    }
    if (tid < 64) {
        sWgx[tid] = W_gx[tid * 64 + tid];
        sbh[tid]  = b_hist[tid];
        sbf[tid]  = b_feat[tid];
        sbgx[tid] = b_gx[tid];
        sbb[tid]  = b_beta[tid];
        sbgh[tid] = b_gh[tid];
    }
    if (tid < 256) sbl[tid] = b_lstm[tid];
    if (tid < 128) { hS[tid] = 0.f; cS[tid] = 0.f; }

    // ---- phase C register weights: k-half `kh`, output column `o` ----
    const int kh = tid >> 8;
    const int o  = tid & 255;
    ull wl2h[32], ul2h[16];
#pragma unroll
    for (int q = 0; q < 32; q++) {
        int gq = 32 * kh + q;
        wl2h[q] = pk2(W_lstm[(2*gq)*256 + o], W_lstm[(2*gq+1)*256 + o]);
    }
#pragma unroll
    for (int q = 0; q < 16; q++) {
        int gq = 16 * kh + q;
        ul2h[q] = pk2(U_lstm[(2*gq)*256 + o], U_lstm[(2*gq+1)*256 + o]);
    }

    // ---- input loader mapping (threads 0..191) ----
    const int ls = tid / 96;
    const int lr = tid % 96;
    const int lc = lr / 32;             // 0=x 1=m 2=d
    const int ll = lr % 32;
    const long lbase = ((long)(2 * bid + ls) * 3 + lc) * TT * 64;

    if (tid < 192) {
        float2 v = *(const float2*)&inputs[lbase + 2 * ll];
        *(float2*)&inb[lc * 128 + ls * 64 + 2 * ll] = v;
    }
    __syncthreads();

    const int g  = tid >> 8;            // phase A half
    const int kq = (tid >> 6) & 3;      // phase A k-quarter
    const int jA = tid & 63;
    const int u  = tid >> 6;            // phase B slice 0..7
    const int jB = tid & 63;

    int p = 0;
    for (int t = 0; t < TT; t++) {
        float* bufc = inb + p * 384;

        float2 pf = make_float2(0.f, 0.f);
        if (tid < 192 && t + 1 < TT)
            pf = *(const float2*)&inputs[lbase + (long)(t + 1) * 64 + 2 * ll];

        // ===== Phase A: x_hat pre (h@W_hist) / gamma_h pre (d@W_gh), k-quartered
        {
            const float* act = g ? (bufc + 256) : hS;
            const float* W   = g ? sWgh2 : sWh2;
            ull acc0 = 0, acc1 = 0;
#pragma unroll
            for (int i = 0; i < 4; i++) {
                int k = kq * 16 + 4 * i, q = k >> 1;
                ulonglong2 a0 = *(const ulonglong2*)&act[k];
                ulonglong2 a1 = *(const ulonglong2*)&act[64 + k];
                ull wa = *(const ull*)&W[(q * 64 + jA) * 2];
                ull wb = *(const ull*)&W[((q + 1) * 64 + jA) * 2];
                FMA2(acc0, wa, a0.x); FMA2(acc0, wb, a0.y);
                FMA2(acc1, wa, a1.x); FMA2(acc1, wb, a1.y);
            }
            float2 r0 = upk(acc0), r1 = upk(acc1);
            pA[(g * 4 + kq) * 128 + jA]      = r0.x + r0.y;
            pA[(g * 4 + kq) * 128 + 64 + jA] = r1.x + r1.y;
        }
        __syncthreads();

        // ===== Phase A2: x_hat/x_c/gamma_x (g0) | gamma_h/h_dec (g1) =====
        if (tid < 256) {
            int r = tid & 127, s = r >> 6, j = r & 63;
            if (tid < 128) {
                float v = pA[r] + pA[128 + r] + pA[256 + r] + pA[384 + r] + sbh[j];
                xhat[r] = v;
                float x = bufc[r], m = bufc[128 + r], d = bufc[256 + r];
                actB[s * 192 + j]       = m * x + (1.f - m) * v;
                actB[s * 192 + 64 + j]  = __expf(-fmaxf(d * sWgx[j] + sbgx[j], 0.f));
                actB[s * 192 + 128 + j] = m;
                long n = 2 * bid + s;
                out[((n * 3 + 0) * (long)TT + t) * 64 + j] = v;
            } else {
                float v = pA[512 + r] + pA[640 + r] + pA[768 + r] + pA[896 + r];
                hdec[r] = hS[r] * __expf(-fmaxf(v + sbgh[j], 0.f));
            }
        }
        __syncthreads();

        // ===== Phase B: fused z_hat + beta over concat [xc|gx|m], 8 slices of 24
        {
            ull accZ0 = 0, accZ1 = 0, accB0 = 0, accB1 = 0;
            const int base  = u * 24;      // float offset into concat space
            const int qbase = u * 12;      // pair offset into sWzb
            if (u < 2) {
#pragma unroll
                for (int i = 0; i < 6; i++) {
                    int off = base + 4 * i;
                    ulonglong2 a0 = *(const ulonglong2*)&actB[off];
                    ulonglong2 a1 = *(const ulonglong2*)&actB[192 + off];
                    ull wa = *(const ull*)&sWzb[((qbase + 2*i) * 64 + jB) * 2];
                    ull wb = *(const ull*)&sWzb[((qbase + 2*i + 1) * 64 + jB) * 2];
                    FMA2(accZ0, wa, a0.x); FMA2(accZ0, wb, a0.y);
                    FMA2(accZ1, wa, a1.x); FMA2(accZ1, wb, a1.y);
                }
                float2 r0 = upk(accZ0), r1 = upk(accZ1);
                pz[u * 128 + jB]      = r0.x + r0.y;
                pz[u * 128 + 64 + jB] = r1.x + r1.y;
            } else if (u == 2) {
#pragma unroll
                for (int i = 0; i < 4; i++) {        // k48..63 -> z_hat
                    int off = base + 4 * i;
                    ulonglong2 a0 = *(const ulonglong2*)&actB[off];
                    ulonglong2 a1 = *(const ulonglong2*)&actB[192 + off];
                    ull wa = *(const ull*)&sWzb[((qbase + 2*i) * 64 + jB) * 2];
                    ull wb = *(const ull*)&sWzb[((qbase + 2*i + 1) * 64 + jB) * 2];
                    FMA2(accZ0, wa, a0.x); FMA2(accZ0, wb, a0.y);
                    FMA2(accZ1, wa, a1.x); FMA2(accZ1, wb, a1.y);
                }
#pragma unroll
                for (int i = 4; i < 6; i++) {        // k64..71 -> beta
                    int off = base + 4 * i;
                    ulonglong2 a0 = *(const ulonglong2*)&actB[off];
                    ulonglong2 a1 = *(const ulonglong2*)&actB[192 + off];
                    ull wa = *(const ull*)&sWzb[((qbase + 2*i) * 64 + jB) * 2];
                    ull wb = *(const ull*)&sWzb[((qbase + 2*i + 1) * 64 + jB) * 2];
                    FMA2(accB0, wa, a0.x); FMA2(accB0, wb, a0.y);
                    FMA2(accB1, wa, a1.x); FMA2(accB1, wb, a1.y);
                }
                float2 rz0 = upk(accZ0), rz1 = upk(accZ1);
                pz[2 * 128 + jB]      = rz0.x + rz0.y;
                pz[2 * 128 + 64 + jB] = rz1.x + rz1.y;
                float2 rb0 = upk(accB0), rb1 = upk(accB1);
                pb[jB]      = rb0.x + rb0.y;
                pb[64 + jB] = rb1.x + rb1.y;
            } else {
#pragma unroll
                for (int i = 0; i < 6; i++) {
                    int off = base + 4 * i;
                    ulonglong2 a0 = *(const ulonglong2*)&actB[off];
                    ulonglong2 a1 = *(const ulonglong2*)&actB[192 + off];
                    ull wa = *(const ull*)&sWzb[((qbase + 2*i) * 64 + jB) * 2];
                    ull wb = *(const ull*)&sWzb[((qbase + 2*i + 1) * 64 + jB) * 2];
                    FMA2(accB0, wa, a0.x); FMA2(accB0, wb, a0.y);
                    FMA2(accB1, wa, a1.x); FMA2(accB1, wb, a1.y);
                }
                float2 r0 = upk(accB0), r1 = upk(accB1);
                pb[(u - 2) * 128 + jB]      = r0.x + r0.y;
                pb[(u - 2) * 128 + 64 + jB] = r1.x + r1.y;
            }
        }
        __syncthreads();

        // ===== Phase B2: beta, c_hat, c_c =====
        if (tid < 128) {
            int s = tid >> 6, j = tid & 63, r = tid;
            float zh   = pz[r] + pz[128 + r] + pz[256 + r] + sbf[j];
            float bpre = pb[r] + pb[128 + r] + pb[256 + r] + pb[384 + r]
                       + pb[512 + r] + pb[640 + r] + sbb[j];
            float beta = 1.f / (1.f + __expf(-bpre));
            float chat = beta * zh + (1.f - beta) * xhat[r];
            float x = bufc[r], m = bufc[128 + r];
            ccm[s * 128 + j]      = m * x + (1.f - m) * chat;
            ccm[s * 128 + 64 + j] = m;
            long n = 2 * bid + s;
            out[((n * 3 + 1) * (long)TT + t) * 64 + j] = zh;
            out[((n * 3 + 2) * (long)TT + t) * 64 + j] = chat;
        }
        __syncthreads();

        // ===== Phase C: z partial = [cc;m]-half @ W_lstm + hdec-half @ U =====
        {
            ull acc0 = 0, acc1 = 0;
#pragma unroll
            for (int i = 0; i < 16; i++) {
                ulonglong2 a0 = *(const ulonglong2*)&ccm[kh * 64 + 4 * i];
                ulonglong2 a1 = *(const ulonglong2*)&ccm[128 + kh * 64 + 4 * i];
                FMA2(acc0, wl2h[2*i], a0.x); FMA2(acc0, wl2h[2*i+1], a0.y);
                FMA2(acc1, wl2h[2*i], a1.x); FMA2(acc1, wl2h[2*i+1], a1.y);
            }
#pragma unroll
            for (int i = 0; i < 8; i++) {
                ulonglong2 a0 = *(const ulonglong2*)&hdec[kh * 32 + 4 * i];
                ulonglong2 a1 = *(const ulonglong2*)&hdec[64 + kh * 32 + 4 * i];
                FMA2(acc0, ul2h[2*i], a0.x); FMA2(acc0, ul2h[2*i+1], a0.y);
                FMA2(acc1, ul2h[2*i], a1.x); FMA2(acc1, ul2h[2*i+1], a1.y);
            }
            float2 r0 = upk(acc0), r1 = upk(acc1);
            pC[(kh * 2 + 0) * 256 + o] = r0.x + r0.y;
            pC[(kh * 2 + 1) * 256 + o] = r1.x + r1.y;
        }
        __syncthreads();

        // ===== Phase C2: reduce k-halves, LSTM gates; commit prefetch =====
        if (tid < 128) {
            int s = tid >> 6, j = tid & 63;
            const float* p0 = pC + s * 256;
            const float* p1 = pC + (2 + s) * 256;
            float z_i = p0[j]       + p1[j]       + sbl[j];
            float z_f = p0[64 + j]  + p1[64 + j]  + sbl[64 + j];
            float z_g = p0[128 + j] + p1[128 + j] + sbl[128 + j];
            float z_o = p0[192 + j] + p1[192 + j] + sbl[192 + j];
            float co = cS[tid];
            float si = 1.f / (1.f + __expf(-z_i));
            float sf = 1.f / (1.f + __expf(-z_f));
            float so = 1.f / (1.f + __expf(-z_o));
            float cn = sf * co + si * tanhf(z_g);
            cS[tid] = cn;
            hS[tid] = so * tanhf(cn);
        }
        if (tid < 192 && t + 1 < TT)
            *(float2*)&inb[(p ^ 1) * 384 + lc * 128 + ls * 64 + 2 * ll] = pf;
        p ^= 1;
        __syncthreads();
    }

    // ===== predictions: sigmoid(h_last @ W_out + b_out) =====
    if (tid < 64) {
        int s = tid >> 5, l = tid & 31;
        float v = hS[s * 64 + l] * W_out[l] + hS[s * 64 + 32 + l] * W_out[32 + l];
#pragma unroll
        for (int off = 16; off; off >>= 1)
            v += __shfl_down_sync(0xffffffffu, v, off);
        if (l == 0)
            out[NIMP + 2 * bid + s] = 1.f / (1.f + __expf(-(v + b_out[0])));
    }
}

extern "C" void kernel_launch(void* const* d_in, const int* in_sizes, int n_in,
                              void* d_out, int out_size)
{
    const float* inputs = (const float*)d_in[0];
    const float* W_hist = (const float*)d_in[1];
    const float* b_hist = (const float*)d_in[2];
    const float* W_feat = (const float*)d_in[3];
    const float* b_feat = (const float*)d_in[4];
    const float* W_gx   = (const float*)d_in[5];
    const float* b_gx   = (const float*)d_in[6];
    const float* W_gh   = (const float*)d_in[7];
    const float* b_gh   = (const float*)d_in[8];
    const float* W_beta = (const float*)d_in[9];
    const float* b_beta = (const float*)d_in[10];
    const float* W_lstm = (const float*)d_in[11];
    const float* U_lstm = (const float*)d_in[12];
    const float* b_lstm = (const float*)d_in[13];
    const float* W_out  = (const float*)d_in[14];
    const float* b_out  = (const float*)d_in[15];

    const int smem_bytes = 26240 * (int)sizeof(float);   // 104,960 B
    cudaFuncSetAttribute(rits_kernel,
                         cudaFuncAttributeMaxDynamicSharedMemorySize, smem_bytes);

    rits_kernel<<<128, 512, smem_bytes>>>(
        inputs, W_hist, b_hist, W_feat, b_feat, W_gx, b_gx, W_gh, b_gh,
        W_beta, b_beta, W_lstm, U_lstm, b_lstm, W_out, b_out,
        (float*)d_out);
}